// round 2
// baseline (speedup 1.0000x reference)
#include <cuda_runtime.h>
#include <math.h>

// Problem constants (fixed-shape problem)
#define D_LVLS 32
#define M_ATOMS 32768
#define NATM (1 + D_LVLS * M_ATOMS)

#define NBLK 64
#define NTHR 512   // NBLK*NTHR == M_ATOMS, one thread per level slot

// Per-node affine 3x4 global HT:
//   [r00 r01 r02 tx][r10 r11 r12 ty][r20 r21 r22 tz]  -> three float4s (48B)
__device__ float4 g_ht[(size_t)NATM * 3];

// Grid barrier state (sense-reversal; replay-safe: blocks snapshot g_sense at entry)
__device__ unsigned g_count = 0;
__device__ unsigned g_sense = 0;

// ---------------------------------------------------------------------------
// Local HT builders
// ---------------------------------------------------------------------------

// Bond HT: Rx(phi_p) @ Rz(theta) @ Tx(d) @ Rx(phi_c), closed form.
// Needs only dof[0..3].
__device__ __forceinline__ void bond_ht4(const float d[4], float r[9], float t[3]) {
    float cp, sp, ct, st, cc, sc;
    __sincosf(d[0], &sp, &cp);
    __sincosf(d[1], &st, &ct);
    __sincosf(d[3], &sc, &cc);
    float dd = d[2];
    r[0] = ct;      r[1] = -st * cc;                 r[2] = st * sc;
    r[3] = cp * st; r[4] = cp * ct * cc - sp * sc;   r[5] = -cp * ct * sc - sp * cc;
    r[6] = sp * st; r[7] = sp * ct * cc + cp * sc;   r[8] = -sp * ct * sc + cp * cc;
    t[0] = ct * dd;
    t[1] = cp * st * dd;
    t[2] = sp * st * dd;
}

// Euler ZYX rotation: Rz(z) @ Ry(y) @ Rx(x)
__device__ __forceinline__ void euler_zyx(float x, float y, float z, float r[9]) {
    float cx, sx, cy, sy, cz, sz;
    __sincosf(x, &sx, &cx);
    __sincosf(y, &sy, &cy);
    __sincosf(z, &sz, &cz);
    r[0] = cz * cy; r[1] = cz * sy * sx - sz * cx; r[2] = cz * sy * cx + sz * sx;
    r[3] = sz * cy; r[4] = sz * sy * sx + cz * cx; r[5] = sz * sy * cx - cz * sx;
    r[6] = -sy;     r[7] = cy * sx;                r[8] = cy * cx;
}

__device__ __forceinline__ void mat3_mul(const float a[9], const float b[9], float c[9]) {
#pragma unroll
    for (int i = 0; i < 3; i++)
#pragma unroll
        for (int j = 0; j < 3; j++)
            c[i * 3 + j] = a[i * 3 + 0] * b[0 * 3 + j]
                         + a[i * 3 + 1] * b[1 * 3 + j]
                         + a[i * 3 + 2] * b[2 * 3 + j];
}

// Jump HT: t = dof[0..2], R = (Rz(d5)Ry(d4)Rx(d3)) @ (Rz(d8)Ry(d7)Rx(d6))
__device__ __forceinline__ void jump_ht(const float dof[9], float r[9], float t[3]) {
    float ra[9], rb[9];
    euler_zyx(dof[3], dof[4], dof[5], ra);
    euler_zyx(dof[6], dof[7], dof[8], rb);
    mat3_mul(ra, rb, r);
    t[0] = dof[0]; t[1] = dof[1]; t[2] = dof[2];
}

// ---------------------------------------------------------------------------
// Persistent kernel: all 32 levels with internal grid barriers
// ---------------------------------------------------------------------------

__global__ void __launch_bounds__(NTHR, 1)
kin_persistent(const float* __restrict__ dofs,
               const int*   __restrict__ nodes,     // [D, M]
               const int*   __restrict__ parents,   // [D, M]
               const int*   __restrict__ doftype,   // [NATM]
               float*       __restrict__ out)       // [NATM, 3]
{
    __shared__ unsigned s_sense;
    if (threadIdx.x == 0) s_sense = *(volatile unsigned*)&g_sense;
    __syncthreads();

    const int i = blockIdx.x * NTHR + threadIdx.x;   // level slot, 0..M-1

    // ---- Root global frame, computed redundantly by every thread (registers)
    float Rr[9], Tr[3];
    {
        float d9[9];
#pragma unroll
        for (int k = 0; k < 9; k++) d9[k] = __ldg(dofs + k);
        if (__ldg(doftype) == 0) {
            jump_ht(d9, Rr, Tr);
        } else {
            float d4[4] = {d9[0], d9[1], d9[2], d9[3]};
            bond_ht4(d4, Rr, Tr);
        }
    }
    if (i == 0) {
        out[0] = Tr[0]; out[1] = Tr[1]; out[2] = Tr[2];
        g_ht[0] = make_float4(Rr[0], Rr[1], Rr[2], Tr[0]);
        g_ht[1] = make_float4(Rr[3], Rr[4], Rr[5], Tr[1]);
        g_ht[2] = make_float4(Rr[6], Rr[7], Rr[8], Tr[2]);
    }

    // ---- Prologue: level-0 inputs
    int   node = __ldg(nodes + i);
    int   par  = __ldg(parents + i);
    int   dt   = __ldg(doftype + node);
    float d4[4];
#pragma unroll
    for (int k = 0; k < 4; k++) d4[k] = __ldg(dofs + (size_t)node * 9 + k);

    for (int l = 0; l < D_LVLS; l++) {
        // Local HT for this level (independent of parent chain)
        float rl[9], tl[3];
        if (dt == 0) {
            float d9[9];
#pragma unroll
            for (int k = 0; k < 9; k++) d9[k] = __ldg(dofs + (size_t)node * 9 + k);
            jump_ht(d9, rl, tl);
        } else {
            bond_ht4(d4, rl, tl);
        }

        // Prefetch next level's inputs (overlaps the barrier wait)
        int nnode = 0, npar = 0, ndt = 1;
        float nd4[4] = {0.f, 0.f, 0.f, 0.f};
        if (l + 1 < D_LVLS) {
            nnode = __ldg(nodes   + (size_t)(l + 1) * M_ATOMS + i);
            npar  = __ldg(parents + (size_t)(l + 1) * M_ATOMS + i);
            ndt   = __ldg(doftype + nnode);
#pragma unroll
            for (int k = 0; k < 4; k++) nd4[k] = __ldg(dofs + (size_t)nnode * 9 + k);
        }

        // Grid barrier (level 0's parents are the in-register root: no barrier)
        if (l > 0) {
            __threadfence();          // make level l-1 stores device-visible
            __syncthreads();
            if (threadIdx.x == 0) {
                unsigned ls = s_sense ^ 1u;
                s_sense = ls;
                if (atomicAdd(&g_count, 1u) == (unsigned)(NBLK - 1)) {
                    *(volatile unsigned*)&g_count = 0u;
                    __threadfence();
                    atomicExch(&g_sense, ls);
                } else {
                    while (*(volatile unsigned*)&g_sense != ls) { }
                }
            }
            __syncthreads();
        }

        // Parent global frame
        float rp[9], tp[3];
        if (par == 0) {
#pragma unroll
            for (int k = 0; k < 9; k++) rp[k] = Rr[k];
            tp[0] = Tr[0]; tp[1] = Tr[1]; tp[2] = Tr[2];
        } else {
            float4 p0 = __ldcg(&g_ht[(size_t)par * 3 + 0]);
            float4 p1 = __ldcg(&g_ht[(size_t)par * 3 + 1]);
            float4 p2 = __ldcg(&g_ht[(size_t)par * 3 + 2]);
            rp[0] = p0.x; rp[1] = p0.y; rp[2] = p0.z; tp[0] = p0.w;
            rp[3] = p1.x; rp[4] = p1.y; rp[5] = p1.z; tp[1] = p1.w;
            rp[6] = p2.x; rp[7] = p2.y; rp[8] = p2.z; tp[2] = p2.w;
        }

        // Compose: Rn = Rp @ Rl ; tn = Rp @ tl + tp
        float rn[9], tn[3];
        mat3_mul(rp, rl, rn);
#pragma unroll
        for (int row = 0; row < 3; row++)
            tn[row] = fmaf(rp[row * 3 + 0], tl[0],
                      fmaf(rp[row * 3 + 1], tl[1],
                      fmaf(rp[row * 3 + 2], tl[2], tp[row])));

        // Store global HT (L2) + output coordinate
        __stcg(&g_ht[(size_t)node * 3 + 0], make_float4(rn[0], rn[1], rn[2], tn[0]));
        __stcg(&g_ht[(size_t)node * 3 + 1], make_float4(rn[3], rn[4], rn[5], tn[1]));
        __stcg(&g_ht[(size_t)node * 3 + 2], make_float4(rn[6], rn[7], rn[8], tn[2]));
        out[(size_t)node * 3 + 0] = tn[0];
        out[(size_t)node * 3 + 1] = tn[1];
        out[(size_t)node * 3 + 2] = tn[2];

        // Rotate pipeline registers
        node = nnode; par = npar; dt = ndt;
#pragma unroll
        for (int k = 0; k < 4; k++) d4[k] = nd4[k];
    }
}

// ---------------------------------------------------------------------------
// Launch
// ---------------------------------------------------------------------------

extern "C" void kernel_launch(void* const* d_in, const int* in_sizes, int n_in,
                              void* d_out, int out_size) {
    const float* dofs          = (const float*)d_in[0];
    const int*   level_nodes   = (const int*)d_in[1];
    const int*   level_parents = (const int*)d_in[2];
    const int*   doftype       = (const int*)d_in[3];
    float*       out           = (float*)d_out;

    kin_persistent<<<NBLK, NTHR>>>(dofs, level_nodes, level_parents, doftype, out);
}